// round 15
// baseline (speedup 1.0000x reference)
#include <cuda_runtime.h>
#include <cuda_bf16.h>
#include <math.h>
#include <stdint.h>

#define NP 1024          // patches
#define CC 4096          // channels
#define NEGV (-1e30f)
#define KSLICES 16       // norm partial slices (256 k each)
#define KP 8             // split-K ways

// ---------------- device scratch ----------------
__device__ float g_par[KP][2u * 1024u * 1024u];   // raw dot partials [kp][z*2^20 + cr*NP + cm]
__device__ float g_normp[KSLICES][2][NP];         // norm partials at COMPACT positions
__device__ float g_cnr[2][NP];                    // rsqrt(norm) at compact positions
__device__ float g_wv[2][NP][2];
__device__ int   g_wi[2][NP][2];
__device__ float g_weights[4];
__device__ int   g_nm;
__device__ int   g_ncol[2];
__device__ int   g_rowidx[NP];
__device__ int   g_colidx[2][NP];
__device__ int   g_dst[2][NP];                    // global patch -> compact slot (or -1) per mat
// COMPACT bf16 split operands: [mat][compact pos][k]. mat0 = G(flag==1), mat1 = Kn(flag==0)
__device__ __nv_bfloat16 g_chi[2][NP][CC];
__device__ __nv_bfloat16 g_clo[2][NP][CC];

// ==================== compaction ====================
__global__ void compact_kernel(const float* __restrict__ mask) {
    __shared__ int wsum1[32], wsum0[32];
    const int n = threadIdx.x;
    const int lane = n & 31, w = n >> 5;
    const int f = (mask[n] == 1.0f) ? 1 : 0;
    const unsigned bal1 = __ballot_sync(0xffffffffu, f);
    const unsigned bal0 = ~bal1;
    const int pre1 = __popc(bal1 & ((1u << lane) - 1u));
    const int pre0 = __popc(bal0 & ((1u << lane) - 1u));
    if (lane == 0) { wsum1[w] = __popc(bal1); wsum0[w] = __popc(bal0); }
    __syncthreads();
    if (w == 0) {
        int v1 = wsum1[lane], o1 = v1;
        int v0 = wsum0[lane], o0 = v0;
        #pragma unroll
        for (int off = 1; off < 32; off <<= 1) {
            int t1 = __shfl_up_sync(0xffffffffu, v1, off);
            int t0 = __shfl_up_sync(0xffffffffu, v0, off);
            if (lane >= off) { v1 += t1; v0 += t0; }
        }
        wsum1[lane] = v1 - o1;
        wsum0[lane] = v0 - o0;
        if (lane == 31) { g_nm = v1; g_ncol[1] = v1; g_ncol[0] = v0; }
    }
    __syncthreads();
    if (f) {
        const int p = wsum1[w] + pre1;
        g_rowidx[p] = n;
        g_colidx[1][p] = n;
        g_dst[0][n] = p;
        g_dst[1][n] = -1;
    } else {
        const int p = wsum0[w] + pre0;
        g_colidx[0][p] = n;
        g_dst[0][n] = -1;
        g_dst[1][n] = p;
    }
    __syncthreads();
    const int nm = g_nm;
    if (n >= nm)      { g_rowidx[n] = 0; g_colidx[1][n] = 0; }
    if (n >= NP - nm) { g_colidx[0][n] = 0; }
}

// ==================== split(compact) + norm partials (double-buffered) ====================
__global__ __launch_bounds__(256) void split_kernel(const float* __restrict__ G,
                                                    const float* __restrict__ Kn) {
    const int mat = blockIdx.z;
    const float* __restrict__ X = mat ? Kn : G;
    __shared__ float tile[2][64][65];
    __shared__ float snorm[4][64];
    __shared__ int s_dst[64];

    const int n0 = blockIdx.x * 64;
    const int kq0 = blockIdx.y * 256;
    const int tid = threadIdx.x;
    const int nn = tid & 63;
    const int kseg = tid >> 6;
    if (tid < 64) s_dst[tid] = g_dst[mat][n0 + tid];
    float norm = 0.f;

    #pragma unroll
    for (int it = 0; it < 4; ++it) {
        const int k0 = kq0 + it * 64;
        float (*tb)[65] = tile[it & 1];
        #pragma unroll
        for (int p = 0; p < 4; ++p) {
            const int r = p * 16 + (tid >> 4);
            const int c = (tid & 15) * 4;
            const size_t gi = (size_t)(k0 + r) * NP + n0 + c;
            const float4 v = *(const float4*)(X + gi);
            tb[r][c]     = v.x;
            tb[r][c + 1] = v.y;
            tb[r][c + 2] = v.z;
            tb[r][c + 3] = v.w;
        }
        __syncthreads();
        const int dst = s_dst[nn];
        if (dst >= 0) {
            float vv[16];
            #pragma unroll
            for (int j = 0; j < 16; ++j) {
                const float v = tb[kseg * 16 + j][nn];
                vv[j] = v;
                norm += v * v;
            }
            __nv_bfloat16 hb[16], lb[16];
            #pragma unroll
            for (int j = 0; j < 16; ++j) {
                const __nv_bfloat16 h = __float2bfloat16(vv[j]);
                hb[j] = h;
                lb[j] = __float2bfloat16(vv[j] - __bfloat162float(h));
            }
            __nv_bfloat16* __restrict__ hd = &g_chi[mat][dst][k0 + kseg * 16];
            __nv_bfloat16* __restrict__ ld = &g_clo[mat][dst][k0 + kseg * 16];
            *(uint4*)(hd)     = *(const uint4*)&hb[0];
            *(uint4*)(hd + 8) = *(const uint4*)&hb[8];
            *(uint4*)(ld)     = *(const uint4*)&lb[0];
            *(uint4*)(ld + 8) = *(const uint4*)&lb[8];
        }
        // no trailing sync: next iteration writes the OTHER buffer; the next
        // barrier (before its read) orders reuse of this one.
    }
    snorm[kseg][nn] = norm;
    __syncthreads();
    if (kseg == 0 && s_dst[nn] >= 0)
        g_normp[blockIdx.y][mat][s_dst[nn]] =
            snorm[0][nn] + snorm[1][nn] + snorm[2][nn] + snorm[3][nn];
}

// ==================== norm combine -> rsqrt tables ====================
__global__ void normr_kernel() {
    const int mat = blockIdx.x;
    const int n = threadIdx.x;
    float s = 0.f;
    #pragma unroll
    for (int q = 0; q < KSLICES; ++q) s += g_normp[q][mat][n];
    g_cnr[mat][n] = rsqrtf(s);
}

// ==================== helpers ====================
__device__ __forceinline__ uint32_t s2u(const void* p) {
    uint32_t a;
    asm("{ .reg .u64 t; cvta.to.shared.u64 t, %1; cvt.u32.u64 %0, t; }" : "=r"(a) : "l"(p));
    return a;
}
#define CP16(dst, src) \
    asm volatile("cp.async.cg.shared.global [%0], [%1], 16;\n" :: "r"(dst), "l"(src))
#define CP_COMMIT() asm volatile("cp.async.commit_group;\n" ::: "memory")

__device__ __forceinline__ uint32_t smaddr(uint32_t base, int row, int chunk) {
    return base + row * 64 + ((chunk ^ ((row >> 1) & 3)) << 4);
}

// ==================== HMMA GEMM + z=1 symmetry + embedded passthrough copy ====================
#define STAGES 4
#define BKC 32
#define NCHUNK 48
#define A_BYTES 8192
#define B_BYTES 4096
#define STAGE_BYTES (A_BYTES + B_BYTES)
#define GEMM_SMEM (STAGES * STAGE_BYTES)   // 48 KB dynamic

__global__ __launch_bounds__(256, 4) void gemm_tc(const float* __restrict__ G,
                                                  const float* __restrict__ Kn,
                                                  float* __restrict__ out) {
    const int rawy = blockIdx.y;
    const int tid = threadIdx.x;
    const int z = blockIdx.z;

    // ---- copy CTAs: rawy in [64,72) -> passthrough G,Kn -> out ----
    if (rawy >= 64) {
        const int ci = ((rawy - 64) * 16 + blockIdx.x) + z * 128;   // 0..255
        const float4* __restrict__ s = (ci < 128)
            ? ((const float4*)G)  + (size_t)ci * 8192
            : ((const float4*)Kn) + (size_t)(ci - 128) * 8192;
        float4* __restrict__ d = ((float4*)out) + (size_t)ci * 8192;
        #pragma unroll 8
        for (int i = 0; i < 32; i++)
            d[i * 256 + tid] = s[i * 256 + tid];
        return;
    }

    const int rt = rawy >> 3;
    const int kp = rawy & 7;
    const int n0 = rt * 128;
    const int m0 = blockIdx.x * 64;
    if (n0 >= g_nm || m0 >= g_ncol[z]) return;
    if (z == 1 && m0 >= n0 + 128) return;        // symmetric: skip strictly-upper tiles

    extern __shared__ __align__(1024) char dsm[];
    const int wid = tid >> 5, lid = tid & 31;
    const uint32_t sbase = s2u(dsm);

    const int wm = wid >> 1;
    const int wn = wid & 1;

    const __nv_bfloat16* __restrict__ Ahi = &g_chi[0][0][0];
    const __nv_bfloat16* __restrict__ Alo = &g_clo[0][0][0];
    const __nv_bfloat16* __restrict__ Bhi = z ? &g_chi[0][0][0] : &g_chi[1][0][0];
    const __nv_bfloat16* __restrict__ Blo = z ? &g_clo[0][0][0] : &g_clo[1][0][0];
    const int kbase = kp * 512;

    auto load_stage = [&](int st, int c) {
        const int ph = c >> 4;
        const int kk = kbase + (c & 15) * BKC;
        const __nv_bfloat16* __restrict__ Ap = (ph == 1) ? Alo : Ahi;
        const __nv_bfloat16* __restrict__ Bp = (ph == 2) ? Blo : Bhi;
        const uint32_t sA = sbase + st * STAGE_BYTES;
        const uint32_t sB = sA + A_BYTES;
        #pragma unroll
        for (int i = 0; i < 2; i++) {
            const int e = tid + (i << 8);
            const int r = e >> 2, cb = e & 3;
            CP16(smaddr(sA, r, cb), Ap + (size_t)(n0 + r) * CC + kk + cb * 8);
        }
        {
            const int r = tid >> 2, cb = tid & 3;
            CP16(smaddr(sB, r, cb), Bp + (size_t)(m0 + r) * CC + kk + cb * 8);
        }
    };

    #pragma unroll
    for (int p = 0; p < STAGES - 1; p++) { load_stage(p, p); CP_COMMIT(); }

    float acc[2][4][4];
    #pragma unroll
    for (int a = 0; a < 2; a++)
        #pragma unroll
        for (int b = 0; b < 4; b++)
            #pragma unroll
            for (int d = 0; d < 4; d++) acc[a][b][d] = 0.f;

    for (int c = 0; c < NCHUNK; c++) {
        const int st = c & (STAGES - 1);
        if (c <= NCHUNK - 3)      asm volatile("cp.async.wait_group 2;\n" ::: "memory");
        else if (c == NCHUNK - 2) asm volatile("cp.async.wait_group 1;\n" ::: "memory");
        else                      asm volatile("cp.async.wait_group 0;\n" ::: "memory");
        __syncthreads();

        const int nc = c + STAGES - 1;
        if (nc < NCHUNK) { load_stage(nc & (STAGES - 1), nc); CP_COMMIT(); }

        const uint32_t sA = sbase + st * STAGE_BYTES;
        const uint32_t sB = sA + A_BYTES;
        #pragma unroll
        for (int ks = 0; ks < 2; ks++) {
            uint32_t af[2][4], bf[4][2];
            #pragma unroll
            for (int mi = 0; mi < 2; mi++) {
                const int row = wm * 32 + mi * 16 + (lid & 15);
                const int ch = ks * 2 + (lid >> 4);
                asm volatile("ldmatrix.sync.aligned.m8n8.x4.shared.b16 {%0,%1,%2,%3}, [%4];"
                             : "=r"(af[mi][0]), "=r"(af[mi][1]), "=r"(af[mi][2]), "=r"(af[mi][3])
                             : "r"(smaddr(sA, row, ch)));
            }
            #pragma unroll
            for (int nip = 0; nip < 2; nip++) {
                const int row = wn * 32 + nip * 16 + ((lid >> 4) & 1) * 8 + (lid & 7);
                const int ch = ks * 2 + ((lid >> 3) & 1);
                asm volatile("ldmatrix.sync.aligned.m8n8.x4.shared.b16 {%0,%1,%2,%3}, [%4];"
                             : "=r"(bf[2 * nip][0]), "=r"(bf[2 * nip][1]),
                               "=r"(bf[2 * nip + 1][0]), "=r"(bf[2 * nip + 1][1])
                             : "r"(smaddr(sB, row, ch)));
            }
            #pragma unroll
            for (int mi = 0; mi < 2; mi++)
                #pragma unroll
                for (int ni = 0; ni < 4; ni++)
                    asm volatile(
                        "mma.sync.aligned.m16n8k16.row.col.f32.bf16.bf16.f32 "
                        "{%0,%1,%2,%3}, {%4,%5,%6,%7}, {%8,%9}, {%0,%1,%2,%3};"
                        : "+f"(acc[mi][ni][0]), "+f"(acc[mi][ni][1]),
                          "+f"(acc[mi][ni][2]), "+f"(acc[mi][ni][3])
                        : "r"(af[mi][0]), "r"(af[mi][1]), "r"(af[mi][2]), "r"(af[mi][3]),
                          "r"(bf[ni][0]), "r"(bf[ni][1]));
        }
    }

    const int g = lid >> 2, tc = lid & 3;
    float* __restrict__ zbase = &g_par[kp][0] + ((size_t)z << 20);

    if (z == 0) {
        #pragma unroll
        for (int mi = 0; mi < 2; mi++) {
            const int r0 = wm * 32 + mi * 16 + g;
            const int r1 = r0 + 8;
            float* __restrict__ p0 = zbase + (size_t)(n0 + r0) * NP + m0;
            float* __restrict__ p1 = zbase + (size_t)(n0 + r1) * NP + m0;
            #pragma unroll
            for (int ni = 0; ni < 4; ni++) {
                const int col = wn * 32 + ni * 8 + 2 * tc;
                float2 o0, o1;
                o0.x = acc[mi][ni][0]; o0.y = acc[mi][ni][1];
                o1.x = acc[mi][ni][2]; o1.y = acc[mi][ni][3];
                *(float2*)(p0 + col) = o0;
                *(float2*)(p1 + col) = o1;
            }
        }
    } else {
        // z=1 symmetric: normal store only C <= R; transposed store (via smem) only R > C
        #pragma unroll
        for (int mi = 0; mi < 2; mi++) {
            const int r0 = wm * 32 + mi * 16 + g;
            const int r1 = r0 + 8;
            const int R0 = n0 + r0, R1 = n0 + r1;
            float* __restrict__ p0 = zbase + (size_t)R0 * NP + m0;
            float* __restrict__ p1 = zbase + (size_t)R1 * NP + m0;
            #pragma unroll
            for (int ni = 0; ni < 4; ni++) {
                const int col = wn * 32 + ni * 8 + 2 * tc;
                const int C0 = m0 + col, C1 = C0 + 1;
                if (C0 <= R0) p0[col]     = acc[mi][ni][0];
                if (C1 <= R0) p0[col + 1] = acc[mi][ni][1];
                if (C0 <= R1) p1[col]     = acc[mi][ni][2];
                if (C1 <= R1) p1[col + 1] = acc[mi][ni][3];
            }
        }
        __syncthreads();          // all stage smem consumption done
        float* __restrict__ smemT = (float*)dsm;
        #pragma unroll
        for (int mi = 0; mi < 2; mi++) {
            const int r0 = wm * 32 + mi * 16 + g;
            const int r1 = r0 + 8;
            #pragma unroll
            for (int ni = 0; ni < 4; ni++) {
                const int col = wn * 32 + ni * 8 + 2 * tc;
                smemT[(col)     * 129 + r0] = acc[mi][ni][0];
                smemT[(col + 1) * 129 + r0] = acc[mi][ni][1];
                smemT[(col)     * 129 + r1] = acc[mi][ni][2];
                smemT[(col + 1) * 129 + r1] = acc[mi][ni][3];
            }
        }
        __syncthreads();
        for (int e = tid; e < 64 * 128; e += 256) {
            const int rl = e & 127, cl = e >> 7;
            if (n0 + rl > m0 + cl)
                zbase[(size_t)(m0 + cl) * NP + n0 + rl] = smemT[cl * 129 + rl];
        }
    }
}

// ==================== block-per-row 8-way reduce + normalize + top-2 ====================
__device__ __forceinline__ void ins2(float v, int idx, float& v1, int& i1, float& v2, int& i2) {
    if (v > v1 || (v == v1 && idx < i1)) { v2 = v1; i2 = i1; v1 = v; i1 = idx; }
    else if (v > v2 || (v == v2 && idx < i2)) { v2 = v; i2 = idx; }
}

__global__ __launch_bounds__(256) void top2_kernel() {
    const int bid = blockIdx.x;
    const int z = bid >> 10, cr = bid & 1023;
    if (cr >= g_nm) return;
    const int cnt = g_ncol[z];
    const int tid = threadIdx.x, lane = tid & 31, wid = tid >> 5;
    const int orig = g_rowidx[cr];
    const float rn = g_cnr[0][cr];
    const float* __restrict__ cnr = z ? g_cnr[0] : g_cnr[1];
    const size_t off = ((size_t)z << 20) + (size_t)cr * NP;

    float v1 = -3.4e38f, v2 = -3.4e38f;
    int i1 = 0x7fffffff, i2 = 0x7fffffff;
    const int m = tid * 4;
    if (m < cnt) {
        float4 s = *(const float4*)(&g_par[0][0] + off + m);
        #pragma unroll
        for (int q = 1; q < KP; q++) {
            const float4 a = *(const float4*)(&g_par[q][0] + off + m);
            s.x += a.x; s.y += a.y; s.z += a.z; s.w += a.w;
        }
        const float4 rc = *(const float4*)(cnr + m);
        float sv[4] = {s.x * rc.x, s.y * rc.y, s.z * rc.z, s.w * rc.w};
        #pragma unroll
        for (int j = 0; j < 4; j++) {
            const float v = (m + j < cnt) ? sv[j] * rn : NEGV;
            if (v > v1) { v2 = v1; i2 = i1; v1 = v; i1 = m + j; }
            else if (v > v2) { v2 = v; i2 = m + j; }
        }
    }
    for (int o = 16; o; o >>= 1) {
        float ov1 = __shfl_down_sync(0xffffffffu, v1, o);
        int   oi1 = __shfl_down_sync(0xffffffffu, i1, o);
        float ov2 = __shfl_down_sync(0xffffffffu, v2, o);
        int   oi2 = __shfl_down_sync(0xffffffffu, i2, o);
        ins2(ov1, oi1, v1, i1, v2, i2);
        ins2(ov2, oi2, v1, i1, v2, i2);
    }
    __shared__ float sv1[8], sv2[8];
    __shared__ int   si1[8], si2[8];
    if (lane == 0) { sv1[wid] = v1; si1[wid] = i1; sv2[wid] = v2; si2[wid] = i2; }
    __syncthreads();
    if (wid == 0) {
        if (lane < 8) { v1 = sv1[lane]; i1 = si1[lane]; v2 = sv2[lane]; i2 = si2[lane]; }
        else { v1 = v2 = -3.4e38f; i1 = i2 = 0x7fffffff; }
        for (int o = 4; o; o >>= 1) {
            float ov1 = __shfl_down_sync(0xffffffffu, v1, o);
            int   oi1 = __shfl_down_sync(0xffffffffu, i1, o);
            float ov2 = __shfl_down_sync(0xffffffffu, v2, o);
            int   oi2 = __shfl_down_sync(0xffffffffu, i2, o);
            ins2(ov1, oi1, v1, i1, v2, i2);
            ins2(ov2, oi2, v1, i1, v2, i2);
        }
        if (lane == 0) {
            g_wv[z][orig][0] = v1;
            g_wv[z][orig][1] = v2;
            g_wi[z][orig][0] = g_colidx[z][i1];
            g_wi[z][orig][1] = g_colidx[z][i2];
        }
    }
}

// ==================== means + softmax ====================
__global__ void weights_kernel(const float* __restrict__ mask) {
    const int n = threadIdx.x;
    const float f = mask[n];
    float s[5];
    s[0] = f;
    s[1] = g_wv[0][n][0] * f;
    s[2] = g_wv[0][n][1] * f;
    s[3] = g_wv[1][n][0] * f;
    s[4] = g_wv[1][n][1] * f;
    __shared__ float sm[5][32];
    __shared__ float tots[5];
    const int lane = n & 31, w = n >> 5;
    #pragma unroll
    for (int k = 0; k < 5; k++) {
        float v = s[k];
        for (int off = 16; off; off >>= 1) v += __shfl_down_sync(0xffffffffu, v, off);
        if (lane == 0) sm[k][w] = v;
    }
    __syncthreads();
    if (w < 5) {
        float v = sm[w][lane];
        for (int off = 16; off; off >>= 1) v += __shfl_down_sync(0xffffffffu, v, off);
        if (lane == 0) tots[w] = v;
    }
    __syncthreads();
    if (n == 0) {
        const float nm = tots[0];
        float mean[4];
        #pragma unroll
        for (int j = 0; j < 4; j++) mean[j] = tots[j + 1] / nm;
        float mx = mean[0];
        #pragma unroll
        for (int j = 1; j < 4; j++) mx = fmaxf(mx, mean[j]);
        float e[4], se = 0.f;
        #pragma unroll
        for (int j = 0; j < 4; j++) { e[j] = expf(mean[j] - mx); se += e[j]; }
        #pragma unroll
        for (int j = 0; j < 4; j++) g_weights[j] = e[j] / se;
    }
}

// ==================== gather: 8 channels per block ====================
__global__ __launch_bounds__(1024) void gather_kernel(const float* __restrict__ G,
                                                      const float* __restrict__ Kn,
                                                      const float* __restrict__ mask,
                                                      float* __restrict__ out) {
    const int c0 = blockIdx.x * 8;
    const int n = threadIdx.x;
    const float w0 = g_weights[0], w1 = g_weights[1], w2 = g_weights[2], w3 = g_weights[3];
    const float f = mask[n];
    const int a0 = g_wi[0][n][0], a1 = g_wi[0][n][1];
    const int b0 = g_wi[1][n][0], b1 = g_wi[1][n][1];
    const bool msk = (f == 1.0f);
    #pragma unroll
    for (int ch = 0; ch < 8; ch++) {
        const int c = c0 + ch;
        const float* __restrict__ kr = Kn + (size_t)c * NP;
        const float* __restrict__ gr = G  + (size_t)c * NP;
        float acc = 0.f;
        if (msk)
            acc = w0 * kr[a0] + w1 * kr[a1] + w2 * gr[b0] + w3 * gr[b1];
        if (n == 0) {
            const float kv = kr[0], gv = gr[0];
            acc += ((msk && a0 == 0) ? 0.f : w0) * kv
                 + ((msk && a1 == 0) ? 0.f : w1) * kv
                 + ((msk && b0 == 0) ? 0.f : w2) * gv
                 + ((msk && b1 == 0) ? 0.f : w3) * gv;
        }
        out[(size_t)(2 * CC + c) * NP + n] = acc;
    }
}

// ==================== launch ====================
extern "C" void kernel_launch(void* const* d_in, const int* in_sizes, int n_in,
                              void* d_out, int out_size) {
    const float* G    = (const float*)d_in[0];
    const float* Kn   = (const float*)d_in[1];
    const float* mask = (const float*)d_in[2];
    float* out = (float*)d_out;

    cudaFuncSetAttribute(gemm_tc, cudaFuncAttributeMaxDynamicSharedMemorySize, GEMM_SMEM);

    compact_kernel<<<1, 1024>>>(mask);
    split_kernel<<<dim3(16, KSLICES, 2), 256>>>(G, Kn);
    normr_kernel<<<2, 1024>>>();
    gemm_tc<<<dim3(16, 72, 2), 256, GEMM_SMEM>>>(G, Kn, out);  // y>=64 -> passthrough copy CTAs
    top2_kernel<<<2048, 256>>>();
    weights_kernel<<<1, 1024>>>(mask);
    gather_kernel<<<512, 1024>>>(G, Kn, mask, out);
}

// round 16
// speedup vs baseline: 1.0725x; 1.0725x over previous
#include <cuda_runtime.h>
#include <cuda_bf16.h>
#include <math.h>
#include <stdint.h>

#define NP 1024          // patches
#define CC 4096          // channels
#define NEGV (-1e30f)
#define KSLICES 16       // norm partial slices (256 k each)
#define KP 8             // split-K ways

// ---------------- device scratch ----------------
__device__ float g_par[KP][2u * 1024u * 1024u];   // raw dot partials [kp][z*2^20 + cr*NP + cm]
__device__ float g_normp[KSLICES][2][NP];         // norm partials at COMPACT positions
__device__ float g_cnr[2][NP];                    // rsqrt(norm) at compact positions
__device__ float g_wv[2][NP][2];
__device__ int   g_wi[2][NP][2];
__device__ float g_weights[4];
__device__ int   g_nm;
__device__ int   g_ncol[2];
__device__ int   g_rowidx[NP];
__device__ int   g_colidx[2][NP];
__device__ int   g_dst[2][NP];                    // global patch -> compact slot (or -1) per mat
// COMPACT bf16 split operands: [mat][compact pos][k]. mat0 = G(flag==1), mat1 = Kn(flag==0)
__device__ __nv_bfloat16 g_chi[2][NP][CC];
__device__ __nv_bfloat16 g_clo[2][NP][CC];

// ==================== compaction ====================
__global__ void compact_kernel(const float* __restrict__ mask) {
    __shared__ int wsum1[32], wsum0[32];
    const int n = threadIdx.x;
    const int lane = n & 31, w = n >> 5;
    const int f = (mask[n] == 1.0f) ? 1 : 0;
    const unsigned bal1 = __ballot_sync(0xffffffffu, f);
    const unsigned bal0 = ~bal1;
    const int pre1 = __popc(bal1 & ((1u << lane) - 1u));
    const int pre0 = __popc(bal0 & ((1u << lane) - 1u));
    if (lane == 0) { wsum1[w] = __popc(bal1); wsum0[w] = __popc(bal0); }
    __syncthreads();
    if (w == 0) {
        int v1 = wsum1[lane], o1 = v1;
        int v0 = wsum0[lane], o0 = v0;
        #pragma unroll
        for (int off = 1; off < 32; off <<= 1) {
            int t1 = __shfl_up_sync(0xffffffffu, v1, off);
            int t0 = __shfl_up_sync(0xffffffffu, v0, off);
            if (lane >= off) { v1 += t1; v0 += t0; }
        }
        wsum1[lane] = v1 - o1;
        wsum0[lane] = v0 - o0;
        if (lane == 31) { g_nm = v1; g_ncol[1] = v1; g_ncol[0] = v0; }
    }
    __syncthreads();
    if (f) {
        const int p = wsum1[w] + pre1;
        g_rowidx[p] = n;
        g_colidx[1][p] = n;
        g_dst[0][n] = p;
        g_dst[1][n] = -1;
    } else {
        const int p = wsum0[w] + pre0;
        g_colidx[0][p] = n;
        g_dst[0][n] = -1;
        g_dst[1][n] = p;
    }
    __syncthreads();
    const int nm = g_nm;
    if (n >= nm)      { g_rowidx[n] = 0; g_colidx[1][n] = 0; }
    if (n >= NP - nm) { g_colidx[0][n] = 0; }
}

// ==================== split(compact) + norm partials (double-buffered) ====================
__global__ __launch_bounds__(256) void split_kernel(const float* __restrict__ G,
                                                    const float* __restrict__ Kn) {
    const int mat = blockIdx.z;
    const float* __restrict__ X = mat ? Kn : G;
    __shared__ float tile[2][64][65];
    __shared__ float snorm[4][64];
    __shared__ int s_dst[64];

    const int n0 = blockIdx.x * 64;
    const int kq0 = blockIdx.y * 256;
    const int tid = threadIdx.x;
    const int nn = tid & 63;
    const int kseg = tid >> 6;
    if (tid < 64) s_dst[tid] = g_dst[mat][n0 + tid];
    float norm = 0.f;

    #pragma unroll
    for (int it = 0; it < 4; ++it) {
        const int k0 = kq0 + it * 64;
        float (*tb)[65] = tile[it & 1];
        #pragma unroll
        for (int p = 0; p < 4; ++p) {
            const int r = p * 16 + (tid >> 4);
            const int c = (tid & 15) * 4;
            const size_t gi = (size_t)(k0 + r) * NP + n0 + c;
            const float4 v = *(const float4*)(X + gi);
            tb[r][c]     = v.x;
            tb[r][c + 1] = v.y;
            tb[r][c + 2] = v.z;
            tb[r][c + 3] = v.w;
        }
        __syncthreads();
        const int dst = s_dst[nn];
        if (dst >= 0) {
            float vv[16];
            #pragma unroll
            for (int j = 0; j < 16; ++j) {
                const float v = tb[kseg * 16 + j][nn];
                vv[j] = v;
                norm += v * v;
            }
            __nv_bfloat16 hb[16], lb[16];
            #pragma unroll
            for (int j = 0; j < 16; ++j) {
                const __nv_bfloat16 h = __float2bfloat16(vv[j]);
                hb[j] = h;
                lb[j] = __float2bfloat16(vv[j] - __bfloat162float(h));
            }
            __nv_bfloat16* __restrict__ hd = &g_chi[mat][dst][k0 + kseg * 16];
            __nv_bfloat16* __restrict__ ld = &g_clo[mat][dst][k0 + kseg * 16];
            *(uint4*)(hd)     = *(const uint4*)&hb[0];
            *(uint4*)(hd + 8) = *(const uint4*)&hb[8];
            *(uint4*)(ld)     = *(const uint4*)&lb[0];
            *(uint4*)(ld + 8) = *(const uint4*)&lb[8];
        }
    }
    snorm[kseg][nn] = norm;
    __syncthreads();
    if (kseg == 0 && s_dst[nn] >= 0)
        g_normp[blockIdx.y][mat][s_dst[nn]] =
            snorm[0][nn] + snorm[1][nn] + snorm[2][nn] + snorm[3][nn];
}

// ==================== norm combine -> rsqrt tables ====================
__global__ void normr_kernel() {
    const int mat = blockIdx.x;
    const int n = threadIdx.x;
    float s = 0.f;
    #pragma unroll
    for (int q = 0; q < KSLICES; ++q) s += g_normp[q][mat][n];
    g_cnr[mat][n] = rsqrtf(s);
}

// ==================== helpers ====================
__device__ __forceinline__ uint32_t s2u(const void* p) {
    uint32_t a;
    asm("{ .reg .u64 t; cvta.to.shared.u64 t, %1; cvt.u32.u64 %0, t; }" : "=r"(a) : "l"(p));
    return a;
}
#define CP16(dst, src) \
    asm volatile("cp.async.cg.shared.global [%0], [%1], 16;\n" :: "r"(dst), "l"(src))
#define CP_COMMIT() asm volatile("cp.async.commit_group;\n" ::: "memory")

__device__ __forceinline__ uint32_t smaddr(uint32_t base, int row, int chunk) {
    return base + row * 64 + ((chunk ^ ((row >> 1) & 3)) << 4);
}

// ==================== HMMA GEMM: 64x64 tiles, 128 threads, split-K 8 ====================
#define STAGES 4
#define BKC 32
#define NCHUNK 48
#define A_BYTES 4096             // 64 rows * 64B
#define B_BYTES 4096
#define STAGE_BYTES (A_BYTES + B_BYTES)
#define GEMM_SMEM (STAGES * STAGE_BYTES)   // 32 KB dynamic

__global__ __launch_bounds__(128) void gemm_tc(const float* __restrict__ G,
                                               const float* __restrict__ Kn,
                                               float* __restrict__ out) {
    const int rawy = blockIdx.y;
    const int tid = threadIdx.x;
    const int z = blockIdx.z;

    // ---- copy CTAs: rawy in [128,136) -> passthrough G,Kn -> out ----
    if (rawy >= 128) {
        const int ci = ((rawy - 128) * 16 + blockIdx.x) + z * 128;   // 0..255
        const float4* __restrict__ s = (ci < 128)
            ? ((const float4*)G)  + (size_t)ci * 8192
            : ((const float4*)Kn) + (size_t)(ci - 128) * 8192;
        float4* __restrict__ d = ((float4*)out) + (size_t)ci * 8192;
        #pragma unroll 8
        for (int i = 0; i < 64; i++)
            d[i * 128 + tid] = s[i * 128 + tid];
        return;
    }

    const int rt = rawy >> 3;        // 0..15
    const int kp = rawy & 7;
    const int n0 = rt * 64;
    const int m0 = blockIdx.x * 64;
    if (n0 >= g_nm || m0 >= g_ncol[z]) return;
    if (z == 1 && m0 >= n0 + 64) return;         // symmetric: skip strictly-upper tiles

    extern __shared__ __align__(1024) char dsm[];
    const int wid = tid >> 5, lid = tid & 31;    // wid 0..3
    const uint32_t sbase = s2u(dsm);

    const int wm = wid >> 1;         // 0..1 -> rows wm*32
    const int wn = wid & 1;          // 0..1 -> cols wn*32

    const __nv_bfloat16* __restrict__ Ahi = &g_chi[0][0][0];
    const __nv_bfloat16* __restrict__ Alo = &g_clo[0][0][0];
    const __nv_bfloat16* __restrict__ Bhi = z ? &g_chi[0][0][0] : &g_chi[1][0][0];
    const __nv_bfloat16* __restrict__ Blo = z ? &g_clo[0][0][0] : &g_clo[1][0][0];
    const int kbase = kp * 512;

    auto load_stage = [&](int st, int c) {
        const int ph = c >> 4;
        const int kk = kbase + (c & 15) * BKC;
        const __nv_bfloat16* __restrict__ Ap = (ph == 1) ? Alo : Ahi;
        const __nv_bfloat16* __restrict__ Bp = (ph == 2) ? Blo : Bhi;
        const uint32_t sA = sbase + st * STAGE_BYTES;
        const uint32_t sB = sA + A_BYTES;
        #pragma unroll
        for (int i = 0; i < 2; i++) {            // A: 64 rows x 4 chunks = 256 ops
            const int e = tid + (i << 7);
            const int r = e >> 2, cb = e & 3;
            CP16(smaddr(sA, r, cb), Ap + (size_t)(n0 + r) * CC + kk + cb * 8);
        }
        #pragma unroll
        for (int i = 0; i < 2; i++) {            // B: 64 rows x 4 chunks
            const int e = tid + (i << 7);
            const int r = e >> 2, cb = e & 3;
            CP16(smaddr(sB, r, cb), Bp + (size_t)(m0 + r) * CC + kk + cb * 8);
        }
    };

    #pragma unroll
    for (int p = 0; p < STAGES - 1; p++) { load_stage(p, p); CP_COMMIT(); }

    float acc[2][4][4];
    #pragma unroll
    for (int a = 0; a < 2; a++)
        #pragma unroll
        for (int b = 0; b < 4; b++)
            #pragma unroll
            for (int d = 0; d < 4; d++) acc[a][b][d] = 0.f;

    for (int c = 0; c < NCHUNK; c++) {
        const int st = c & (STAGES - 1);
        if (c <= NCHUNK - 3)      asm volatile("cp.async.wait_group 2;\n" ::: "memory");
        else if (c == NCHUNK - 2) asm volatile("cp.async.wait_group 1;\n" ::: "memory");
        else                      asm volatile("cp.async.wait_group 0;\n" ::: "memory");
        __syncthreads();

        const int nc = c + STAGES - 1;
        if (nc < NCHUNK) { load_stage(nc & (STAGES - 1), nc); CP_COMMIT(); }

        const uint32_t sA = sbase + st * STAGE_BYTES;
        const uint32_t sB = sA + A_BYTES;
        #pragma unroll
        for (int ks = 0; ks < 2; ks++) {
            uint32_t af[2][4], bf[4][2];
            #pragma unroll
            for (int mi = 0; mi < 2; mi++) {
                const int row = wm * 32 + mi * 16 + (lid & 15);
                const int ch = ks * 2 + (lid >> 4);
                asm volatile("ldmatrix.sync.aligned.m8n8.x4.shared.b16 {%0,%1,%2,%3}, [%4];"
                             : "=r"(af[mi][0]), "=r"(af[mi][1]), "=r"(af[mi][2]), "=r"(af[mi][3])
                             : "r"(smaddr(sA, row, ch)));
            }
            #pragma unroll
            for (int nip = 0; nip < 2; nip++) {
                const int row = wn * 32 + nip * 16 + ((lid >> 4) & 1) * 8 + (lid & 7);
                const int ch = ks * 2 + ((lid >> 3) & 1);
                asm volatile("ldmatrix.sync.aligned.m8n8.x4.shared.b16 {%0,%1,%2,%3}, [%4];"
                             : "=r"(bf[2 * nip][0]), "=r"(bf[2 * nip][1]),
                               "=r"(bf[2 * nip + 1][0]), "=r"(bf[2 * nip + 1][1])
                             : "r"(smaddr(sB, row, ch)));
            }
            #pragma unroll
            for (int mi = 0; mi < 2; mi++)
                #pragma unroll
                for (int ni = 0; ni < 4; ni++)
                    asm volatile(
                        "mma.sync.aligned.m16n8k16.row.col.f32.bf16.bf16.f32 "
                        "{%0,%1,%2,%3}, {%4,%5,%6,%7}, {%8,%9}, {%0,%1,%2,%3};"
                        : "+f"(acc[mi][ni][0]), "+f"(acc[mi][ni][1]),
                          "+f"(acc[mi][ni][2]), "+f"(acc[mi][ni][3])
                        : "r"(af[mi][0]), "r"(af[mi][1]), "r"(af[mi][2]), "r"(af[mi][3]),
                          "r"(bf[ni][0]), "r"(bf[ni][1]));
        }
    }

    const int g = lid >> 2, tc = lid & 3;
    float* __restrict__ zbase = &g_par[kp][0] + ((size_t)z << 20);

    if (z == 0) {
        #pragma unroll
        for (int mi = 0; mi < 2; mi++) {
            const int r0 = wm * 32 + mi * 16 + g;
            const int r1 = r0 + 8;
            float* __restrict__ p0 = zbase + (size_t)(n0 + r0) * NP + m0;
            float* __restrict__ p1 = zbase + (size_t)(n0 + r1) * NP + m0;
            #pragma unroll
            for (int ni = 0; ni < 4; ni++) {
                const int col = wn * 32 + ni * 8 + 2 * tc;
                float2 o0, o1;
                o0.x = acc[mi][ni][0]; o0.y = acc[mi][ni][1];
                o1.x = acc[mi][ni][2]; o1.y = acc[mi][ni][3];
                *(float2*)(p0 + col) = o0;
                *(float2*)(p1 + col) = o1;
            }
        }
    } else {
        // z=1 symmetric: normal store only C <= R; transposed store (via smem) only R > C
        #pragma unroll
        for (int mi = 0; mi < 2; mi++) {
            const int r0 = wm * 32 + mi * 16 + g;
            const int r1 = r0 + 8;
            const int R0 = n0 + r0, R1 = n0 + r1;
            float* __restrict__ p0 = zbase + (size_t)R0 * NP + m0;
            float* __restrict__ p1 = zbase + (size_t)R1 * NP + m0;
            #pragma unroll
            for (int ni = 0; ni < 4; ni++) {
                const int col = wn * 32 + ni * 8 + 2 * tc;
                const int C0 = m0 + col, C1 = C0 + 1;
                if (C0 <= R0) p0[col]     = acc[mi][ni][0];
                if (C1 <= R0) p0[col + 1] = acc[mi][ni][1];
                if (C0 <= R1) p1[col]     = acc[mi][ni][2];
                if (C1 <= R1) p1[col + 1] = acc[mi][ni][3];
            }
        }
        __syncthreads();          // all stage smem consumption done
        float* __restrict__ smemT = (float*)dsm;   // 64 x 64, pitch 65 (16.6 KB < 32 KB)
        #pragma unroll
        for (int mi = 0; mi < 2; mi++) {
            const int r0 = wm * 32 + mi * 16 + g;
            const int r1 = r0 + 8;
            #pragma unroll
            for (int ni = 0; ni < 4; ni++) {
                const int col = wn * 32 + ni * 8 + 2 * tc;
                smemT[(col)     * 65 + r0] = acc[mi][ni][0];
                smemT[(col + 1) * 65 + r0] = acc[mi][ni][1];
                smemT[(col)     * 65 + r1] = acc[mi][ni][2];
                smemT[(col + 1) * 65 + r1] = acc[mi][ni][3];
            }
        }
        __syncthreads();
        for (int e = tid; e < 64 * 64; e += 128) {
            const int rl = e & 63, cl = e >> 6;
            if (n0 + rl > m0 + cl)
                zbase[(size_t)(m0 + cl) * NP + n0 + rl] = smemT[cl * 65 + rl];
        }
    }
}

// ==================== block-per-row 8-way reduce + normalize + top-2 ====================
__device__ __forceinline__ void ins2(float v, int idx, float& v1, int& i1, float& v2, int& i2) {
    if (v > v1 || (v == v1 && idx < i1)) { v2 = v1; i2 = i1; v1 = v; i1 = idx; }
    else if (v > v2 || (v == v2 && idx < i2)) { v2 = v; i2 = idx; }
}

__global__ __launch_bounds__(256) void top2_kernel() {
    const int bid = blockIdx.x;
    const int z = bid >> 10, cr = bid & 1023;
    if (cr >= g_nm) return;
    const int cnt = g_ncol[z];
    const int tid = threadIdx.x, lane = tid & 31, wid = tid >> 5;
    const int orig = g_rowidx[cr];
    const float rn = g_cnr[0][cr];
    const float* __restrict__ cnr = z ? g_cnr[0] : g_cnr[1];
    const size_t off = ((size_t)z << 20) + (size_t)cr * NP;

    float v1 = -3.4e38f, v2 = -3.4e38f;
    int i1 = 0x7fffffff, i2 = 0x7fffffff;
    const int m = tid * 4;
    if (m < cnt) {
        float4 s = *(const float4*)(&g_par[0][0] + off + m);
        #pragma unroll
        for (int q = 1; q < KP; q++) {
            const float4 a = *(const float4*)(&g_par[q][0] + off + m);
            s.x += a.x; s.y += a.y; s.z += a.z; s.w += a.w;
        }
        const float4 rc = *(const float4*)(cnr + m);
        float sv[4] = {s.x * rc.x, s.y * rc.y, s.z * rc.z, s.w * rc.w};
        #pragma unroll
        for (int j = 0; j < 4; j++) {
            const float v = (m + j < cnt) ? sv[j] * rn : NEGV;
            if (v > v1) { v2 = v1; i2 = i1; v1 = v; i1 = m + j; }
            else if (v > v2) { v2 = v; i2 = m + j; }
        }
    }
    for (int o = 16; o; o >>= 1) {
        float ov1 = __shfl_down_sync(0xffffffffu, v1, o);
        int   oi1 = __shfl_down_sync(0xffffffffu, i1, o);
        float ov2 = __shfl_down_sync(0xffffffffu, v2, o);
        int   oi2 = __shfl_down_sync(0xffffffffu, i2, o);
        ins2(ov1, oi1, v1, i1, v2, i2);
        ins2(ov2, oi2, v1, i1, v2, i2);
    }
    __shared__ float sv1[8], sv2[8];
    __shared__ int   si1[8], si2[8];
    if (lane == 0) { sv1[wid] = v1; si1[wid] = i1; sv2[wid] = v2; si2[wid] = i2; }
    __syncthreads();
    if (wid == 0) {
        if (lane < 8) { v1 = sv1[lane]; i1 = si1[lane]; v2 = sv2[lane]; i2 = si2[lane]; }
        else { v1 = v2 = -3.4e38f; i1 = i2 = 0x7fffffff; }
        for (int o = 4; o; o >>= 1) {
            float ov1 = __shfl_down_sync(0xffffffffu, v1, o);
            int   oi1 = __shfl_down_sync(0xffffffffu, i1, o);
            float ov2 = __shfl_down_sync(0xffffffffu, v2, o);
            int   oi2 = __shfl_down_sync(0xffffffffu, i2, o);
            ins2(ov1, oi1, v1, i1, v2, i2);
            ins2(ov2, oi2, v1, i1, v2, i2);
        }
        if (lane == 0) {
            g_wv[z][orig][0] = v1;
            g_wv[z][orig][1] = v2;
            g_wi[z][orig][0] = g_colidx[z][i1];
            g_wi[z][orig][1] = g_colidx[z][i2];
        }
    }
}

// ==================== means + softmax ====================
__global__ void weights_kernel(const float* __restrict__ mask) {
    const int n = threadIdx.x;
    const float f = mask[n];
    float s[5];
    s[0] = f;
    s[1] = g_wv[0][n][0] * f;
    s[2] = g_wv[0][n][1] * f;
    s[3] = g_wv[1][n][0] * f;
    s[4] = g_wv[1][n][1] * f;
    __shared__ float sm[5][32];
    __shared__ float tots[5];
    const int lane = n & 31, w = n >> 5;
    #pragma unroll
    for (int k = 0; k < 5; k++) {
        float v = s[k];
        for (int off = 16; off; off >>= 1) v += __shfl_down_sync(0xffffffffu, v, off);
        if (lane == 0) sm[k][w] = v;
    }
    __syncthreads();
    if (w < 5) {
        float v = sm[w][lane];
        for (int off = 16; off; off >>= 1) v += __shfl_down_sync(0xffffffffu, v, off);
        if (lane == 0) tots[w] = v;
    }
    __syncthreads();
    if (n == 0) {
        const float nm = tots[0];
        float mean[4];
        #pragma unroll
        for (int j = 0; j < 4; j++) mean[j] = tots[j + 1] / nm;
        float mx = mean[0];
        #pragma unroll
        for (int j = 1; j < 4; j++) mx = fmaxf(mx, mean[j]);
        float e[4], se = 0.f;
        #pragma unroll
        for (int j = 0; j < 4; j++) { e[j] = expf(mean[j] - mx); se += e[j]; }
        #pragma unroll
        for (int j = 0; j < 4; j++) g_weights[j] = e[j] / se;
    }
}

// ==================== gather: 8 channels per block ====================
__global__ __launch_bounds__(1024) void gather_kernel(const float* __restrict__ G,
                                                      const float* __restrict__ Kn,
                                                      const float* __restrict__ mask,
                                                      float* __restrict__ out) {
    const int c0 = blockIdx.x * 8;
    const int n = threadIdx.x;
    const float w0 = g_weights[0], w1 = g_weights[1], w2 = g_weights[2], w3 = g_weights[3];
    const float f = mask[n];
    const int a0 = g_wi[0][n][0], a1 = g_wi[0][n][1];
    const int b0 = g_wi[1][n][0], b1 = g_wi[1][n][1];
    const bool msk = (f == 1.0f);
    #pragma unroll
    for (int ch = 0; ch < 8; ch++) {
        const int c = c0 + ch;
        const float* __restrict__ kr = Kn + (size_t)c * NP;
        const float* __restrict__ gr = G  + (size_t)c * NP;
        float acc = 0.f;
        if (msk)
            acc = w0 * kr[a0] + w1 * kr[a1] + w2 * gr[b0] + w3 * gr[b1];
        if (n == 0) {
            const float kv = kr[0], gv = gr[0];
            acc += ((msk && a0 == 0) ? 0.f : w0) * kv
                 + ((msk && a1 == 0) ? 0.f : w1) * kv
                 + ((msk && b0 == 0) ? 0.f : w2) * gv
                 + ((msk && b1 == 0) ? 0.f : w3) * gv;
        }
        out[(size_t)(2 * CC + c) * NP + n] = acc;
    }
}

// ==================== launch ====================
extern "C" void kernel_launch(void* const* d_in, const int* in_sizes, int n_in,
                              void* d_out, int out_size) {
    const float* G    = (const float*)d_in[0];
    const float* Kn   = (const float*)d_in[1];
    const float* mask = (const float*)d_in[2];
    float* out = (float*)d_out;

    cudaFuncSetAttribute(gemm_tc, cudaFuncAttributeMaxDynamicSharedMemorySize, GEMM_SMEM);

    compact_kernel<<<1, 1024>>>(mask);
    split_kernel<<<dim3(16, KSLICES, 2), 256>>>(G, Kn);
    normr_kernel<<<2, 1024>>>();
    gemm_tc<<<dim3(16, 136, 2), 128, GEMM_SMEM>>>(G, Kn, out);  // y>=128 -> copy CTAs
    top2_kernel<<<2048, 256>>>();
    weights_kernel<<<1, 1024>>>(mask);
    gather_kernel<<<512, 1024>>>(G, Kn, mask, out);
}